// round 8
// baseline (speedup 1.0000x reference)
#include <cuda_runtime.h>
#include <cuda_bf16.h>
#include <math.h>
#include <stdint.h>

#define NT     20000
#define K1DIM  20001
#define BB     64
#define H4     1024
#define HD     256
#define EPSF   1e-5f
#define FF     128
#define TT     16

#define S1   35
#define CPS1 9
#define S2   16
#define S3   16
#define S4   4

// ---------------- scratch (floats) -----------------------------------------
#define OFF_CNT    0
#define OFF_H      1280000
#define OFF_H2     (OFF_H + 65536)
#define OFF_D1     (OFF_H2 + 65536)
#define OFF_STATS  (OFF_D1 + 65536)
#define OFF_P1     (OFF_STATS + 128)
#define OFF_P2     (OFF_P1 + S1 * BB * H4)
#define OFF_P3     (OFF_P2 + S2 * BB * H4)
#define OFF_P4     (OFF_P3 + S3 * BB * HD)
#define SCRATCH_N  (OFF_P4 + S4 * BB * H4)

__device__ __align__(16) float g_scratch[SCRATCH_N];

// ---------------- helpers ---------------------------------------------------
__device__ __forceinline__ uint32_t smem_u32(const void* p) {
    uint32_t a;
    asm("{ .reg .u64 t; cvta.to.shared.u64 t, %1; cvt.u32.u64 %0, t; }" : "=r"(a) : "l"(p));
    return a;
}
__device__ __forceinline__ void ldsm4(uint32_t (&r)[4], uint32_t addr) {
    asm volatile("ldmatrix.sync.aligned.m8n8.x4.shared.b16 {%0,%1,%2,%3}, [%4];"
                 : "=r"(r[0]), "=r"(r[1]), "=r"(r[2]), "=r"(r[3]) : "r"(addr));
}
__device__ __forceinline__ void mma16816(float* c, const uint32_t* a,
                                         uint32_t b0, uint32_t b1) {
    asm volatile("mma.sync.aligned.m16n8k16.row.col.f32.bf16.bf16.f32 "
                 "{%0,%1,%2,%3}, {%4,%5,%6,%7}, {%8,%9}, {%0,%1,%2,%3};"
                 : "+f"(c[0]), "+f"(c[1]), "+f"(c[2]), "+f"(c[3])
                 : "r"(a[0]), "r"(a[1]), "r"(a[2]), "r"(a[3]), "r"(b0), "r"(b1));
}
__device__ __forceinline__ void split_bf16(float v, unsigned short& h, unsigned short& l) {
    __nv_bfloat16 hb = __float2bfloat16(v);
    float hf = __bfloat162float(hb);
    __nv_bfloat16 lb = __float2bfloat16(v - hf);
    h = *reinterpret_cast<unsigned short*>(&hb);
    l = *reinterpret_cast<unsigned short*>(&lb);
}
__device__ __forceinline__ float gelu_exact(float x) {
    return 0.5f * x * (1.0f + erff(x * 0.70710678118654752f));
}

// smem byte offsets (per buffer): A hi 0, A lo 8192, W hi 16384, W lo 32768
#define SM_AH 0
#define SM_AL 8192
#define SM_BH 16384
#define SM_BL 32768
#define G_SMEM_BYTES 49152

// ---------------- front-end kernels ----------------------------------------
__global__ void k_zero() {
    int i = blockIdx.x * blockDim.x + threadIdx.x;
    int stride = gridDim.x * blockDim.x;
    for (; i < BB * NT; i += stride) g_scratch[OFF_CNT + i] = 0.0f;
}

__global__ void k_count(const int* __restrict__ tags) {
    int r = blockIdx.x * blockDim.x + threadIdx.x;
    if (r >= BB * FF) return;
    int b = r / FF;
    const int* t = tags + r * TT;
    int v[TT];
#pragma unroll
    for (int i = 0; i < TT; i++) v[i] = t[i];
    float* cnt = &g_scratch[OFF_CNT] + (long long)b * NT;
#pragma unroll
    for (int i = 0; i < TT; i++) {
        bool dup = false;
#pragma unroll
        for (int j = 0; j < TT; j++)
            if (j < i && v[j] == v[i]) dup = true;
        if (!dup) atomicAdd(&cnt[v[i]], 1.0f);
    }
}

__global__ void k_stats() {
    int b = blockIdx.x;
    const float* cnt = &g_scratch[OFF_CNT] + (long long)b * NT;
    float s = 0.0f, s2 = 0.0f;
    for (int i = threadIdx.x; i < NT; i += blockDim.x) {
        float v = cnt[i]; s += v; s2 += v * v;
    }
    __shared__ float sh[256], sh2[256];
    sh[threadIdx.x] = s; sh2[threadIdx.x] = s2;
    __syncthreads();
    for (int o = 128; o > 0; o >>= 1) {
        if (threadIdx.x < o) { sh[threadIdx.x] += sh[threadIdx.x + o]; sh2[threadIdx.x] += sh2[threadIdx.x + o]; }
        __syncthreads();
    }
    if (threadIdx.x == 0) {
        float mu  = sh[0] / (float)NT;
        float var = sh2[0] / (float)NT - mu * mu;
        g_scratch[OFF_STATS + b * 2]     = mu;
        g_scratch[OFF_STATS + b * 2 + 1] = rsqrtf(var + EPSF);
    }
}

__global__ void k_y(const float* __restrict__ fc, const float* __restrict__ lg,
                    const float* __restrict__ lb, float* __restrict__ yout) {
    int idx = blockIdx.x * blockDim.x + threadIdx.x;
    if (idx >= BB * K1DIM) return;
    int b = idx / K1DIM, k = idx - b * K1DIM;
    float val;
    if (k == 0) {
        val = fc[b] * 0.01f;
    } else {
        float mu = g_scratch[OFF_STATS + b * 2];
        float r  = g_scratch[OFF_STATS + b * 2 + 1];
        float c  = g_scratch[OFF_CNT + (long long)b * NT + (k - 1)];
        val = (c - mu) * r * lg[k - 1] + lb[k - 1];
    }
    yout[idx] = val;
}

// ---------------- HMMA GEMM -------------------------------------------------
// D[b 0..63][jbase + 0..127] (+)= sum_k Act[b][k] * W[k][j], 3-term bf16 split.
__global__ __launch_bounds__(256)
void g_mma(const float* __restrict__ W, const float* __restrict__ Bext, int b_off,
           float* __restrict__ out_ext, int p_off, const float* __restrict__ bias,
           int K, int N, int cps) {
    extern __shared__ char sm[];
    uint32_t sb = smem_u32(sm);
    int tid = threadIdx.x, lane = tid & 31, warp = tid >> 5;
    int wm = warp & 3, wn = warp >> 2;
    const float* Act = Bext ? Bext : (g_scratch + b_off);

    int s = blockIdx.y;
    int jbase = blockIdx.x * 128;
    int totC = (K + 63) >> 6;
    int cBeg = s * cps;
    int cEnd = min(cBeg + cps, totC);

    float acc[8][4];
#pragma unroll
    for (int f = 0; f < 8; f++)
#pragma unroll
        for (int e = 0; e < 4; e++) acc[f][e] = 0.0f;

    for (int ch = cBeg; ch < cEnd; ch++) {
        int k0 = ch << 6;
        // ---- W tile: [128 j][64 k] bf16 hi/lo, swizzled; conflict-free STS ----
        {
            int jj = lane & 7, kq = lane >> 3;             // kq 0..3
#pragma unroll
            for (int i = 0; i < 16; i++) {
                int bi = i * 8 + warp;
                int jblk = bi & 15, kblk = bi >> 4;        // kblk 0..7
                int j  = jblk * 8 + jj;
                int kk = kblk * 8 + kq * 2;
                int gj = jbase + j, gk = k0 + kk;
                float v0 = 0.f, v1 = 0.f;
                if (gj < N) {
                    if (gk < K)     v0 = W[(size_t)gk * N + gj];
                    if (gk + 1 < K) v1 = W[(size_t)(gk + 1) * N + gj];
                }
                unsigned short h0, l0, h1, l1;
                split_bf16(v0, h0, l0);
                split_bf16(v1, h1, l1);
                uint32_t off = (uint32_t)(j * 128 + (((kk >> 3) ^ (j & 7)) << 4) + (kk & 7) * 2);
                *(uint32_t*)(sm + SM_BH + off) = (uint32_t)h0 | ((uint32_t)h1 << 16);
                *(uint32_t*)(sm + SM_BL + off) = (uint32_t)l0 | ((uint32_t)l1 << 16);
            }
        }
        // ---- Act tile: [64 b][64 k] bf16 hi/lo ----
        {
            int kq = lane & 7, bb = lane >> 3;             // bb 0..3
#pragma unroll
            for (int i = 0; i < 8; i++) {
                int bi = i * 8 + warp;
                int bblk = bi & 15, kblk = bi >> 4;        // kblk 0..3
                int b  = bblk * 4 + bb;
                int kk = kblk * 16 + kq * 2;
                int gk = k0 + kk;
                float v0 = (gk < K)     ? Act[(size_t)b * K + gk]     : 0.f;
                float v1 = (gk + 1 < K) ? Act[(size_t)b * K + gk + 1] : 0.f;
                unsigned short h0, l0, h1, l1;
                split_bf16(v0, h0, l0);
                split_bf16(v1, h1, l1);
                uint32_t off = (uint32_t)(b * 128 + (((kk >> 3) ^ (b & 7)) << 4) + (kk & 7) * 2);
                *(uint32_t*)(sm + SM_AH + off) = (uint32_t)h0 | ((uint32_t)h1 << 16);
                *(uint32_t*)(sm + SM_AL + off) = (uint32_t)l0 | ((uint32_t)l1 << 16);
            }
        }
        __syncthreads();

#pragma unroll
        for (int ks = 0; ks < 4; ks++) {
            uint32_t ah[4], al[4];
            {
                int r = wm * 16 + (lane & 15);
                int u = ks * 2 + (lane >> 4);
                uint32_t ad = sb + SM_AH + (uint32_t)(r * 128 + ((u ^ (r & 7)) << 4));
                ldsm4(ah, ad);
                ldsm4(al, ad + (SM_AL - SM_AH));
            }
#pragma unroll
            for (int jb = 0; jb < 4; jb++) {
                uint32_t bh[4], bl[4];
                int jr = wn * 64 + jb * 16 + (lane & 7) + ((lane >> 4) << 3);
                int u = ks * 2 + ((lane >> 3) & 1);
                uint32_t bd = sb + SM_BH + (uint32_t)(jr * 128 + ((u ^ (jr & 7)) << 4));
                ldsm4(bh, bd);
                ldsm4(bl, bd + (SM_BL - SM_BH));
                mma16816(acc[jb * 2],     ah, bh[0], bh[1]);
                mma16816(acc[jb * 2],     al, bh[0], bh[1]);
                mma16816(acc[jb * 2],     ah, bl[0], bl[1]);
                mma16816(acc[jb * 2 + 1], ah, bh[2], bh[3]);
                mma16816(acc[jb * 2 + 1], al, bh[2], bh[3]);
                mma16816(acc[jb * 2 + 1], ah, bl[2], bl[3]);
            }
        }
        __syncthreads();
    }

    // ---- epilogue: natural [b][j] stores (partial buffer or final + bias) ----
    float* outp = out_ext ? out_ext : (g_scratch + p_off);
    int rowbase = out_ext ? 0 : s * BB;
#pragma unroll
    for (int f = 0; f < 8; f++) {
        int j = jbase + wn * 64 + f * 8 + (lane & 3) * 2;
        int b = wm * 16 + (lane >> 2);
        float bv0 = 0.f, bv1 = 0.f;
        if (bias) {
            if (j < N)     bv0 = bias[j];
            if (j + 1 < N) bv1 = bias[j + 1];
        }
        float* p0 = outp + (size_t)(rowbase + b) * N + j;
        float* p1 = outp + (size_t)(rowbase + b + 8) * N + j;
        if (j < N)     { p0[0] = acc[f][0] + bv0; p1[0] = acc[f][2] + bv0; }
        if (j + 1 < N) { p0[1] = acc[f][1] + bv1; p1[1] = acc[f][3] + bv1; }
    }
}

// ---------------- reduce / activation kernels ------------------------------
__global__ void k_eln(const float* __restrict__ b1, const float* __restrict__ lg,
                      const float* __restrict__ lb) {
    int b = blockIdx.x, j = threadIdx.x;   // 1024 threads
    __shared__ float red[32];
    __shared__ float bc[2];
    float x = b1[j];
    for (int sl = 0; sl < S1; sl++)
        x += g_scratch[OFF_P1 + ((sl * BB + b) << 10) + j];
    float g = gelu_exact(x);

    float v = g;
#pragma unroll
    for (int o = 16; o > 0; o >>= 1) v += __shfl_xor_sync(0xFFFFFFFFu, v, o);
    if ((j & 31) == 0) red[j >> 5] = v;
    __syncthreads();
    if (j < 32) {
        float t = red[j];
#pragma unroll
        for (int o = 16; o > 0; o >>= 1) t += __shfl_xor_sync(0xFFFFFFFFu, t, o);
        if (j == 0) bc[0] = t * (1.0f / (float)H4);
    }
    __syncthreads();
    float mu = bc[0];
    float d = g - mu;
    v = d * d;
#pragma unroll
    for (int o = 16; o > 0; o >>= 1) v += __shfl_xor_sync(0xFFFFFFFFu, v, o);
    if ((j & 31) == 0) red[j >> 5] = v;
    __syncthreads();
    if (j < 32) {
        float t = red[j];
#pragma unroll
        for (int o = 16; o > 0; o >>= 1) t += __shfl_xor_sync(0xFFFFFFFFu, t, o);
        if (j == 0) bc[1] = rsqrtf(t * (1.0f / (float)H4) + EPSF);
    }
    __syncthreads();
    g_scratch[OFF_H + (b << 10) + j] = d * bc[1] * lg[j] + lb[j];
}

__global__ void k_gelu(int p_off, int S, const float* __restrict__ bias,
                       int out_off, int N) {
    int idx = blockIdx.x * blockDim.x + threadIdx.x;
    if (idx >= BB * N) return;
    int b = idx / N, j = idx - b * N;
    float x = bias[j];
    for (int sl = 0; sl < S; sl++)
        x += g_scratch[p_off + (long long)(sl * BB + b) * N + j];
    g_scratch[out_off + idx] = gelu_exact(x);
}

__global__ void k_enc(const float* __restrict__ be2, float* __restrict__ enc_out) {
    int idx = blockIdx.x * blockDim.x + threadIdx.x;
    if (idx >= BB * HD) return;
    int b = idx / HD, j = idx - b * HD;
    float v = be2[j];
    for (int sl = 0; sl < S3; sl++)
        v += g_scratch[OFF_P3 + (long long)(sl * BB + b) * HD + j];
    enc_out[idx] = v;
}

// ===========================================================================
extern "C" void kernel_launch(void* const* d_in, const int* in_sizes, int n_in,
                              void* d_out, int out_size) {
    const int*   tags  = (const int*)d_in[0];
    const float* fc    = (const float*)d_in[1];
    const float* ln_g  = (const float*)d_in[2];
    const float* ln_b  = (const float*)d_in[3];
    const float* w1    = (const float*)d_in[4];
    const float* b1    = (const float*)d_in[5];
    const float* ln2_g = (const float*)d_in[6];
    const float* ln2_b = (const float*)d_in[7];
    const float* we1   = (const float*)d_in[8];
    const float* be1   = (const float*)d_in[9];
    const float* we2   = (const float*)d_in[10];
    const float* be2   = (const float*)d_in[11];
    const float* wd1   = (const float*)d_in[12];
    const float* bd1   = (const float*)d_in[13];
    const float* wd2   = (const float*)d_in[14];
    const float* bd2   = (const float*)d_in[15];

    float* out     = (float*)d_out;
    float* y_out   = out;                          // [64][20001]
    float* enc_out = out + (long long)BB * K1DIM;  // [64][256]
    float* dec_out = enc_out + (long long)BB * HD; // [64][20001]

    cudaFuncSetAttribute(g_mma, cudaFuncAttributeMaxDynamicSharedMemorySize, G_SMEM_BYTES);

    k_zero<<<512, 256>>>();
    k_count<<<(BB * FF + 127) / 128, 128>>>(tags);
    k_stats<<<BB, 256>>>();
    k_y<<<(BB * K1DIM + 255) / 256, 256>>>(fc, ln_g, ln_b, y_out);

    // G1: y[64,20001] @ w1[20001,1024] -> P1 (8 jt x 35 slices, 9 chunks each)
    g_mma<<<dim3(8, S1), 256, G_SMEM_BYTES>>>(w1, y_out, 0, nullptr, OFF_P1,
                                              nullptr, K1DIM, H4, CPS1);
    k_eln<<<BB, 1024>>>(b1, ln2_g, ln2_b);

    // G2: h @ we1[1024,1024] -> P2 (8 jt x 16 slices, 1 chunk)
    g_mma<<<dim3(8, S2), 256, G_SMEM_BYTES>>>(we1, nullptr, OFF_H, nullptr, OFF_P2,
                                              nullptr, H4, H4, 1);
    k_gelu<<<(BB * H4 + 255) / 256, 256>>>(OFF_P2, S2, be1, OFF_H2, H4);

    // G3: h2 @ we2[1024,256] -> P3 (2 jt x 16 slices, 1 chunk)
    g_mma<<<dim3(2, S3), 256, G_SMEM_BYTES>>>(we2, nullptr, OFF_H2, nullptr, OFF_P3,
                                              nullptr, H4, HD, 1);
    k_enc<<<(BB * HD + 255) / 256, 256>>>(be2, enc_out);

    // G4: enc @ wd1[256,1024] -> P4 (8 jt x 4 slices, 1 chunk)
    g_mma<<<dim3(8, S4), 256, G_SMEM_BYTES>>>(wd1, enc_out, 0, nullptr, OFF_P4,
                                              nullptr, HD, H4, 1);
    k_gelu<<<(BB * H4 + 255) / 256, 256>>>(OFF_P4, S4, bd1, OFF_D1, H4);

    // G5: d1 @ wd2[1024,20001] -> dec_out + bias (157 jt, all 16 chunks)
    g_mma<<<dim3(157, 1), 256, G_SMEM_BYTES>>>(wd2, nullptr, OFF_D1, dec_out, 0,
                                               bd2, H4, K1DIM, 16);
}

// round 10
// speedup vs baseline: 1.9329x; 1.9329x over previous
#include <cuda_runtime.h>
#include <math.h>

#define NT     20000
#define K1DIM  20001
#define BB     64
#define FF     128
#define TT     16
#define H4     1024
#define HD     256
#define EPSF   1e-5f

// split-K slice counts
#define S1 55
#define S2 16
#define S3 32
#define S4 8
#define S5 2
#define NS5 20002   // padded (even) partial stride for GEMM5

// ---------------- scratch layout (floats) ---------------------------------
#define OFF_CNT    0            // 64*20000 = 1,280,000
#define OFF_YT     1280000      // 20001*64 = 1,280,064
#define OFF_HT     2560064      // 1024*64
#define OFF_H2T    2625600      // 1024*64
#define OFF_ENCT   2691136      // 256*64
#define OFF_D1T    2707520      // 1024*64
#define OFF_STATS  2773056      // 64*2
#define OFF_P1     2773184      // 55*64*1024 = 3,604,480
#define OFF_P2     6377664      // 16*64*1024 = 1,048,576
#define OFF_P3     7426240      // 32*64*256  =   524,288
#define OFF_P4     7950528      // 8*64*1024  =   524,288
#define OFF_P5     8474816      // 2*64*20002 = 2,560,256
#define SCRATCH_N  11035072

__device__ __align__(16) float g_scratch[SCRATCH_N];

// ---------------- packed fp32x2 FMA ----------------------------------------
__device__ __forceinline__ void ffma2(unsigned long long& c,
                                      unsigned long long a,
                                      unsigned long long b) {
    asm("fma.rn.f32x2 %0, %1, %2, %0;" : "+l"(c) : "l"(a), "l"(b));
}
__device__ __forceinline__ unsigned long long dup2(float v) {
    float2 t; t.x = v; t.y = v;
    return *reinterpret_cast<unsigned long long*>(&t);
}
__device__ __forceinline__ float gelu_exact(float x) {
    return 0.5f * x * (1.0f + erff(x * 0.70710678118654752f));
}

// ---------------- K0: zero tag counts --------------------------------------
__global__ void k_zero() {
    int i = blockIdx.x * blockDim.x + threadIdx.x;
    int stride = gridDim.x * blockDim.x;
    for (; i < BB * NT; i += stride) g_scratch[OFF_CNT + i] = 0.0f;
}

// ---------------- K1: dedupe-scatter counts --------------------------------
__global__ void k_count(const int* __restrict__ tags) {
    int r = blockIdx.x * blockDim.x + threadIdx.x;
    if (r >= BB * FF) return;
    int b = r / FF;
    const int* t = tags + r * TT;
    int v[TT];
#pragma unroll
    for (int i = 0; i < TT; i++) v[i] = t[i];
    float* cnt = &g_scratch[OFF_CNT] + (long long)b * NT;
#pragma unroll
    for (int i = 0; i < TT; i++) {
        bool dup = false;
#pragma unroll
        for (int j = 0; j < TT; j++)
            if (j < i && v[j] == v[i]) dup = true;
        if (!dup) atomicAdd(&cnt[v[i]], 1.0f);
    }
}

// ---------------- K2: per-batch mean / rstd --------------------------------
__global__ void k_stats() {
    int b = blockIdx.x;
    const float* cnt = &g_scratch[OFF_CNT] + (long long)b * NT;
    float s = 0.0f, s2 = 0.0f;
    for (int i = threadIdx.x; i < NT; i += blockDim.x) {
        float v = cnt[i];
        s += v; s2 += v * v;
    }
    __shared__ float sh[256], sh2[256];
    sh[threadIdx.x] = s; sh2[threadIdx.x] = s2;
    __syncthreads();
    for (int o = 128; o > 0; o >>= 1) {
        if (threadIdx.x < o) { sh[threadIdx.x] += sh[threadIdx.x + o]; sh2[threadIdx.x] += sh2[threadIdx.x + o]; }
        __syncthreads();
    }
    if (threadIdx.x == 0) {
        float mu  = sh[0] / (float)NT;
        float var = sh2[0] / (float)NT - mu * mu;
        g_scratch[OFF_STATS + b * 2]     = mu;
        g_scratch[OFF_STATS + b * 2 + 1] = rsqrtf(var + EPSF);
    }
}

// ---------------- K3: build y + yT (2D grid, no div) ------------------------
__global__ void k_y(const float* __restrict__ fc, const float* __restrict__ lg,
                    const float* __restrict__ lb, float* __restrict__ yout) {
    int b = blockIdx.y;
    int k = blockIdx.x * blockDim.x + threadIdx.x;
    if (k >= K1DIM) return;
    float val;
    if (k == 0) {
        val = fc[b] * 0.01f;
    } else {
        float mu = g_scratch[OFF_STATS + b * 2];
        float r  = g_scratch[OFF_STATS + b * 2 + 1];
        float c  = g_scratch[OFF_CNT + (long long)b * NT + (k - 1)];
        val = (c - mu) * r * lg[k - 1] + lb[k - 1];
    }
    yout[(long long)b * K1DIM + k] = val;
    g_scratch[OFF_YT + (long long)k * BB + b] = val;
}

// ---------------- tiled GEMM with register prefetch -------------------------
// partial[s][64][Ns] = AT[K][64]^T @ W[K][N] for the block's k-slice.
// 128 threads; block tile 128 j x 64 b; thread tile 8 j (4 pairs) x 8 b.
__global__ __launch_bounds__(128, 3)
void k_gemm(int at_off, const float* __restrict__ W, int p_off,
            int K, int N, int Ns, int kPerSlice) {
    __shared__ float ws[16][128];
    __shared__ float ys[16][64];
    const float* AT = &g_scratch[at_off];

    int jbase  = blockIdx.x * 128;
    int s      = blockIdx.y;
    int kstart = s * kPerSlice;
    int kend   = min(kstart + kPerSlice, K);
    int tid = threadIdx.x;
    int jg = tid & 15;         // 16 j-groups
    int bg = tid >> 4;         // 8 b-groups

    unsigned long long acc[4][8];
#pragma unroll
    for (int p = 0; p < 4; p++)
#pragma unroll
        for (int i = 0; i < 8; i++) acc[p][i] = 0ull;

    bool vecW = ((N & 3) == 0) && (jbase + 128 <= N);

    if (vecW) {
        // ---- software-pipelined path: prefetch tile t+1 during tile t MMA ----
        float4 wr[4], yr[2];
        {
            int kc = kstart;
#pragma unroll
            for (int i = 0; i < 4; i++) {
                int idx = tid + 128 * i;
                int row = idx >> 5, col = (idx & 31) * 4;
                int kg  = kc + row;
                wr[i] = (kg < kend)
                      ? *reinterpret_cast<const float4*>(&W[(long long)kg * N + jbase + col])
                      : make_float4(0.f, 0.f, 0.f, 0.f);
            }
#pragma unroll
            for (int i = 0; i < 2; i++) {
                int idx = tid + 128 * i;
                int row = idx >> 4, col = (idx & 15) * 4;
                int kg  = kc + row;
                yr[i] = (kg < kend)
                      ? *reinterpret_cast<const float4*>(&AT[(long long)kg * BB + col])
                      : make_float4(0.f, 0.f, 0.f, 0.f);
            }
        }
        for (int kc = kstart; kc < kend; kc += 16) {
            // STS current tile
#pragma unroll
            for (int i = 0; i < 4; i++) {
                int idx = tid + 128 * i;
                int row = idx >> 5, col = (idx & 31) * 4;
                *reinterpret_cast<float4*>(&ws[row][col]) = wr[i];
            }
#pragma unroll
            for (int i = 0; i < 2; i++) {
                int idx = tid + 128 * i;
                int row = idx >> 4, col = (idx & 15) * 4;
                *reinterpret_cast<float4*>(&ys[row][col]) = yr[i];
            }
            __syncthreads();
            // prefetch next tile (LDG latency overlaps the MMA below)
            int kn = kc + 16;
            if (kn < kend) {
#pragma unroll
                for (int i = 0; i < 4; i++) {
                    int idx = tid + 128 * i;
                    int row = idx >> 5, col = (idx & 31) * 4;
                    int kg  = kn + row;
                    wr[i] = (kg < kend)
                          ? *reinterpret_cast<const float4*>(&W[(long long)kg * N + jbase + col])
                          : make_float4(0.f, 0.f, 0.f, 0.f);
                }
#pragma unroll
                for (int i = 0; i < 2; i++) {
                    int idx = tid + 128 * i;
                    int row = idx >> 4, col = (idx & 15) * 4;
                    int kg  = kn + row;
                    yr[i] = (kg < kend)
                          ? *reinterpret_cast<const float4*>(&AT[(long long)kg * BB + col])
                          : make_float4(0.f, 0.f, 0.f, 0.f);
                }
            }
            // MMA on smem tile
#pragma unroll
            for (int kk = 0; kk < 16; kk++) {
                unsigned long long wv[4];
#pragma unroll
                for (int p = 0; p < 4; p++)
                    wv[p] = *reinterpret_cast<const unsigned long long*>(&ws[kk][2 * (jg + 16 * p)]);
                float4 ya = *reinterpret_cast<const float4*>(&ys[kk][bg * 8]);
                float4 yb = *reinterpret_cast<const float4*>(&ys[kk][bg * 8 + 4]);
                unsigned long long yd[8];
                yd[0] = dup2(ya.x); yd[1] = dup2(ya.y); yd[2] = dup2(ya.z); yd[3] = dup2(ya.w);
                yd[4] = dup2(yb.x); yd[5] = dup2(yb.y); yd[6] = dup2(yb.z); yd[7] = dup2(yb.w);
#pragma unroll
                for (int p = 0; p < 4; p++)
#pragma unroll
                    for (int i = 0; i < 8; i++)
                        ffma2(acc[p][i], wv[p], yd[i]);
            }
            __syncthreads();
        }
    } else {
        // ---- scalar fallback (edge j-tile only) ----
        for (int kc = kstart; kc < kend; kc += 16) {
#pragma unroll
            for (int i = 0; i < 16; i++) {
                int idx = tid + 128 * i;
                int row = idx >> 7;
                int col = idx & 127;
                int kg  = kc + row;
                int j   = jbase + col;
                ws[row][col] = (kg < kend && j < N) ? W[(long long)kg * N + j] : 0.0f;
            }
#pragma unroll
            for (int i = 0; i < 2; i++) {
                int idx = tid + 128 * i;
                int row = idx >> 4;
                int col = (idx & 15) * 4;
                int kg  = kc + row;
                float4 v = make_float4(0.f, 0.f, 0.f, 0.f);
                if (kg < kend)
                    v = *reinterpret_cast<const float4*>(&AT[(long long)kg * BB + col]);
                *reinterpret_cast<float4*>(&ys[row][col]) = v;
            }
            __syncthreads();
#pragma unroll
            for (int kk = 0; kk < 16; kk++) {
                unsigned long long wv[4];
#pragma unroll
                for (int p = 0; p < 4; p++)
                    wv[p] = *reinterpret_cast<const unsigned long long*>(&ws[kk][2 * (jg + 16 * p)]);
                float4 ya = *reinterpret_cast<const float4*>(&ys[kk][bg * 8]);
                float4 yb = *reinterpret_cast<const float4*>(&ys[kk][bg * 8 + 4]);
                unsigned long long yd[8];
                yd[0] = dup2(ya.x); yd[1] = dup2(ya.y); yd[2] = dup2(ya.z); yd[3] = dup2(ya.w);
                yd[4] = dup2(yb.x); yd[5] = dup2(yb.y); yd[6] = dup2(yb.z); yd[7] = dup2(yb.w);
#pragma unroll
                for (int p = 0; p < 4; p++)
#pragma unroll
                    for (int i = 0; i < 8; i++)
                        ffma2(acc[p][i], wv[p], yd[i]);
            }
            __syncthreads();
        }
    }

    // epilogue: store partial[s][b][j..j+1]
    float* P = &g_scratch[p_off];
#pragma unroll
    for (int p = 0; p < 4; p++) {
        int j0 = jbase + 2 * (jg + 16 * p);
        if (j0 >= N) continue;
#pragma unroll
        for (int i = 0; i < 8; i++) {
            int b = bg * 8 + i;
            *reinterpret_cast<float2*>(&P[(long long)(s * BB + b) * Ns + j0]) =
                *reinterpret_cast<float2*>(&acc[p][i]);
        }
    }
}

// ---------------- reduce P1 + bias + GELU + LayerNorm(1024) -> hT ----------
__global__ void k_eln(const float* __restrict__ b1, const float* __restrict__ lg,
                      const float* __restrict__ lb) {
    int b = blockIdx.x;
    __shared__ float vals[H4];
    __shared__ float red[256];
    float ssum = 0.0f;
    for (int j = threadIdx.x; j < H4; j += 256) {
        float x = b1[j];
        for (int sl = 0; sl < S1; sl++)
            x += g_scratch[OFF_P1 + (long long)(sl * BB + b) * H4 + j];
        float g = gelu_exact(x);
        vals[j] = g; ssum += g;
    }
    red[threadIdx.x] = ssum; __syncthreads();
    for (int o = 128; o > 0; o >>= 1) {
        if (threadIdx.x < o) red[threadIdx.x] += red[threadIdx.x + o];
        __syncthreads();
    }
    float mu = red[0] / (float)H4;
    __syncthreads();
    float s2 = 0.0f;
    for (int j = threadIdx.x; j < H4; j += 256) { float d = vals[j] - mu; s2 += d * d; }
    red[threadIdx.x] = s2; __syncthreads();
    for (int o = 128; o > 0; o >>= 1) {
        if (threadIdx.x < o) red[threadIdx.x] += red[threadIdx.x + o];
        __syncthreads();
    }
    float r = rsqrtf(red[0] / (float)H4 + EPSF);
    for (int j = threadIdx.x; j < H4; j += 256)
        g_scratch[OFF_HT + (long long)j * BB + b] = (vals[j] - mu) * r * lg[j] + lb[j];
}

// ---------------- reduce partials + bias + GELU + transpose ----------------
__global__ void k_gelu_t(int p_off, int S, const float* __restrict__ bias,
                         int out_off, int N) {
    int idx = blockIdx.x * blockDim.x + threadIdx.x;
    if (idx >= BB * N) return;
    int b = idx / N, j = idx - b * N;
    float x = bias[j];
    for (int sl = 0; sl < S; sl++)
        x += g_scratch[p_off + (long long)(sl * BB + b) * N + j];
    g_scratch[out_off + (long long)j * BB + b] = gelu_exact(x);
}

// ---------------- enc epilogue: reduce + bias -> d_out + encT --------------
__global__ void k_enc(const float* __restrict__ be2, float* __restrict__ enc_out) {
    int idx = blockIdx.x * blockDim.x + threadIdx.x;
    if (idx >= BB * HD) return;
    int b = idx / HD, j = idx - b * HD;
    float v = be2[j];
    for (int sl = 0; sl < S3; sl++)
        v += g_scratch[OFF_P3 + (long long)(sl * BB + b) * HD + j];
    enc_out[idx] = v;
    g_scratch[OFF_ENCT + (long long)j * BB + b] = v;
}

// ---------------- dec epilogue: reduce + bias -> d_out ---------------------
__global__ void k_dec(const float* __restrict__ bd2, float* __restrict__ dec_out) {
    int idx = blockIdx.x * blockDim.x + threadIdx.x;
    if (idx >= BB * K1DIM) return;
    int b = idx / K1DIM, j = idx - b * K1DIM;
    float v = bd2[j];
#pragma unroll
    for (int sl = 0; sl < S5; sl++)
        v += g_scratch[OFF_P5 + (long long)(sl * BB + b) * NS5 + j];
    dec_out[idx] = v;
}

// ---------------------------------------------------------------------------
extern "C" void kernel_launch(void* const* d_in, const int* in_sizes, int n_in,
                              void* d_out, int out_size) {
    const int*   tags  = (const int*)d_in[0];
    const float* fc    = (const float*)d_in[1];
    const float* ln_g  = (const float*)d_in[2];
    const float* ln_b  = (const float*)d_in[3];
    const float* w1    = (const float*)d_in[4];
    const float* b1    = (const float*)d_in[5];
    const float* ln2_g = (const float*)d_in[6];
    const float* ln2_b = (const float*)d_in[7];
    const float* we1   = (const float*)d_in[8];
    const float* be1   = (const float*)d_in[9];
    const float* we2   = (const float*)d_in[10];
    const float* be2   = (const float*)d_in[11];
    const float* wd1   = (const float*)d_in[12];
    const float* bd1   = (const float*)d_in[13];
    const float* wd2   = (const float*)d_in[14];
    const float* bd2   = (const float*)d_in[15];

    float* out     = (float*)d_out;
    float* y_out   = out;                          // [64][20001]
    float* enc_out = out + (long long)BB * K1DIM;  // [64][256]
    float* dec_out = enc_out + (long long)BB * HD; // [64][20001]

    k_zero<<<512, 256>>>();
    k_count<<<(BB * FF + 127) / 128, 128>>>(tags);
    k_stats<<<BB, 256>>>();
    k_y<<<dim3((K1DIM + 255) / 256, BB), 256>>>(fc, ln_g, ln_b, y_out);

    // G1: y[64,20001] @ w1 -> P1   (8 jt x 55 ks, kps=368; 440 blocks = 1 wave)
    k_gemm<<<dim3(8, S1), 128>>>(OFF_YT, w1, OFF_P1, K1DIM, H4, H4, 368);
    k_eln<<<BB, 256>>>(b1, ln2_g, ln2_b);

    // G2: h @ we1 -> P2            (8 jt x 16 ks, kps=64)
    k_gemm<<<dim3(8, S2), 128>>>(OFF_HT, we1, OFF_P2, H4, H4, H4, 64);
    k_gelu_t<<<(BB * H4 + 255) / 256, 256>>>(OFF_P2, S2, be1, OFF_H2T, H4);

    // G3: h2 @ we2 -> P3           (2 jt x 32 ks, kps=32)
    k_gemm<<<dim3(2, S3), 128>>>(OFF_H2T, we2, OFF_P3, H4, HD, HD, 32);
    k_enc<<<(BB * HD + 255) / 256, 256>>>(be2, enc_out);

    // G4: enc @ wd1 -> P4          (8 jt x 8 ks, kps=32)
    k_gemm<<<dim3(8, S4), 128>>>(OFF_ENCT, wd1, OFF_P4, HD, H4, H4, 32);
    k_gelu_t<<<(BB * H4 + 255) / 256, 256>>>(OFF_P4, S4, bd1, OFF_D1T, H4);

    // G5: d1 @ wd2 -> P5           (157 jt x 2 ks, kps=512; 314 blocks = 1 wave)
    k_gemm<<<dim3(157, S5), 128>>>(OFF_D1T, wd2, OFF_P5, H4, K1DIM, NS5, 512);
    k_dec<<<(BB * K1DIM + 255) / 256, 256>>>(bd2, dec_out);
}